// round 17
// baseline (speedup 1.0000x reference)
#include <cuda_runtime.h>
#include <cuda_bf16.h>
#include <cstddef>

// Problem constants (fixed by the reference setup)
#define BB      16
#define TRED    512
#define CC      512
#define C4      (CC / 4)   // float4 per row = 128
#define TT      64         // t-rows per tile
#define NTH     512        // threads per block
#define NWARP   (NTH / 32) // 16
#define RPW     (NTH / C4) // 4 rows per wave
#define NJ      (TT / RPW) // 16 waves per thread per tile
#define GX      28         // persistent blocks per batch: 28*16=448 ≈ one wave @ occ 3

// Persistent one-wave kernel.
//   Each block owns batch b = blockIdx.y, scans durations[b] ONCE (shfl scan,
//   3 syncs), then grid-strides over t-tiles of that batch:
//     padding tile (t0 >= curr_len): stream zeros + mask, no search, no sync
//     real tile: tid<TT searchsorted into double-buffered seg smem (1 sync),
//                then batched-4 LDG.128/STG.128 gather (MLP=4/thread).
__global__ __launch_bounds__(NTH)
void upsample_persist(const float* __restrict__ px,
                      const int*   __restrict__ dur,
                      const int*   __restrict__ target_T,
                      float*       __restrict__ out,
                      int max_len, int ntiles, int write_mask)
{
    __shared__ int csum[TRED];
    __shared__ int wsum[NWARP];
    __shared__ int seg_s[2][TT];

    const int b    = blockIdx.y;
    const int tid  = threadIdx.x;
    const int lane = tid & 31;
    const int wid  = tid >> 5;

    // ---- inclusive scan of durations[b] (once per block, 3 syncs) ----
    int x = dur[b * TRED + tid];
    #pragma unroll
    for (int off = 1; off < 32; off <<= 1) {
        int y = __shfl_up_sync(0xffffffffu, x, off);
        if (lane >= off) x += y;
    }
    if (lane == 31) wsum[wid] = x;
    __syncthreads();
    if (wid == 0) {
        int w = (lane < NWARP) ? wsum[lane] : 0;
        #pragma unroll
        for (int off = 1; off < NWARP; off <<= 1) {
            int y = __shfl_up_sync(0xffffffffu, w, off);
            if (lane >= off) w += y;
        }
        if (lane < NWARP) wsum[lane] = w;
    }
    __syncthreads();
    csum[tid] = x + ((wid > 0) ? wsum[wid - 1] : 0);
    __syncthreads();

    const int total    = csum[TRED - 1];
    const int curr_len = min(total, target_T[b]);

    const int row = tid >> 7;        // 0..3
    const int c4  = tid & (C4 - 1);  // 0..127
    const float4* pxb      = (const float4*)px + (size_t)b * TRED * C4 + c4;
    float4*       base_out = (float4*)out + (size_t)b * max_len * C4 + c4;
    float*        mask     = out + (size_t)BB * max_len * CC;
    const float4  Z        = make_float4(0.0f, 0.0f, 0.0f, 0.0f);

    int buf = 0;

    for (int tile = blockIdx.x; tile < ntiles; tile += GX) {
        const int  t0   = tile * TT;
        const bool full = (t0 + TT <= max_len);
        float4* outp = base_out + (size_t)(t0 + row) * C4;

        // ---------- pure-padding tile: zeros + mask, no search/sync ----------
        if (t0 >= curr_len) {
            if (write_mask && tid < TT && t0 + tid < max_len)
                mask[(size_t)b * max_len + t0 + tid] = 1.0f;
            if (full) {
                #pragma unroll
                for (int j = 0; j < NJ; j++)
                    outp[(size_t)j * RPW * C4] = Z;
            } else {
                #pragma unroll
                for (int j = 0; j < NJ; j++)
                    if (t0 + row + j * RPW < max_len)
                        outp[(size_t)j * RPW * C4] = Z;
            }
            continue;
        }

        // ---------- real tile: searchsorted (tid<TT) + gather ----------
        if (tid < TT) {
            const int t     = t0 + tid;
            const int valid = (t < max_len) && (t < curr_len);
            int seg = -1;
            if (valid) {
                int lo = 0, hi = TRED;               // first i with csum[i] > t
                while (lo < hi) {
                    int mid = (lo + hi) >> 1;
                    if (csum[mid] > t) hi = mid; else lo = mid + 1;
                }
                seg = min(lo, TRED - 1);
            }
            seg_s[buf][tid] = seg;
            if (write_mask && t < max_len)
                mask[(size_t)b * max_len + t] = valid ? 0.0f : 1.0f;
        }
        __syncthreads();

        const int* sb = seg_s[buf];
        if (full) {
            #pragma unroll
            for (int j = 0; j < NJ; j += 4) {
                const int s0 = sb[row + (j + 0) * RPW];
                const int s1 = sb[row + (j + 1) * RPW];
                const int s2 = sb[row + (j + 2) * RPW];
                const int s3 = sb[row + (j + 3) * RPW];
                float4 v0 = (s0 >= 0) ? pxb[(size_t)s0 * C4] : Z;
                float4 v1 = (s1 >= 0) ? pxb[(size_t)s1 * C4] : Z;
                float4 v2 = (s2 >= 0) ? pxb[(size_t)s2 * C4] : Z;
                float4 v3 = (s3 >= 0) ? pxb[(size_t)s3 * C4] : Z;
                outp[(size_t)(j + 0) * RPW * C4] = v0;
                outp[(size_t)(j + 1) * RPW * C4] = v1;
                outp[(size_t)(j + 2) * RPW * C4] = v2;
                outp[(size_t)(j + 3) * RPW * C4] = v3;
            }
        } else {
            #pragma unroll
            for (int j = 0; j < NJ; j++) {
                const int t = t0 + row + j * RPW;
                if (t >= max_len) continue;
                const int s = sb[row + j * RPW];
                float4 v = (s >= 0) ? pxb[(size_t)s * C4] : Z;
                outp[(size_t)j * RPW * C4] = v;
            }
        }
        buf ^= 1;   // double buffer: next real tile writes the other slot
    }
}

extern "C" void kernel_launch(void* const* d_in, const int* in_sizes, int n_in,
                              void* d_out, int out_size)
{
    const float* px  = (const float*)d_in[0];   // pooled_x  (B, T_RED, C) f32
    const int*   dur = (const int*)  d_in[1];   // durations (B, T_RED)   i32
    const int*   tgt = (const int*)  d_in[2];   // target_T  (B,)         i32

    // Recover max_len from out_size. Layout: [x (B*max_len*C)] ++ [mask (B*max_len)].
    int max_len, write_mask;
    if (out_size % (BB * (CC + 1)) == 0) {
        max_len    = out_size / (BB * (CC + 1));
        write_mask = 1;
    } else {
        max_len    = out_size / (BB * CC);   // fallback: x-only output
        write_mask = 0;
    }

    const int ntiles = (max_len + TT - 1) / TT;
    dim3 grid((ntiles < GX) ? ntiles : GX, BB);
    upsample_persist<<<grid, NTH>>>(px, dur, tgt, (float*)d_out,
                                    max_len, ntiles, write_mask);
}